// round 12
// baseline (speedup 1.0000x reference)
#include <cuda_runtime.h>
#include <cuda_bf16.h>
#include <math.h>

// Problem constants
#define BATCH 4
#define NPTS  8192
#define CCH   128      // channels
#define KIN1  131      // C + 3
#define KNN   20
#define TP    64       // points per GEMM tile

// Scratch (allocation-free rule: __device__ globals)
__device__ float g_normals[BATCH * 3 * NPTS];           // [B,3,N]
__device__ float g_h[BATCH * CCH * NPTS];               // [B,C,N]
__device__ float g_scale[CCH];
__device__ float g_shift[CCH];

// ===========================================================================
// LAPACK-faithful 3x3 symmetric eigensolver: ssytrd + sorgtr + ssteqr
// (the exact path jnp.linalg.eigh -> ssyevd takes for n=3).
// Returns the eigenvector of the SMALLEST eigenvalue, with LAPACK's sign.
// ===========================================================================
__device__ __forceinline__ float signf(float a, float b) {
    // Fortran SIGN(a,b) as gfortran compiles it (copysign)
    return copysignf(fabsf(a), b);
}

__device__ __forceinline__ float lapy2f(float x, float y) {
    float xa = fabsf(x), ya = fabsf(y);
    float w = fmaxf(xa, ya), z = fminf(xa, ya);
    if (z == 0.0f) return w;
    float r = z / w;
    return w * sqrtf(1.0f + r * r);
}

// LAPACK >= 3.10 slartg (c >= 0, r carries sign of f)
__device__ __forceinline__ void slartg(float f, float g, float& c, float& s, float& r) {
    if (g == 0.0f)      { c = 1.0f; s = 0.0f; r = f; }
    else if (f == 0.0f) { c = 0.0f; s = signf(1.0f, g); r = fabsf(g); }
    else {
        float dd = sqrtf(f * f + g * g);
        c = fabsf(f) / dd;
        r = signf(dd, f);
        s = g / r;
    }
}

__device__ __forceinline__ void slaev2(float a, float b, float c,
                                       float& rt1, float& rt2, float& cs1, float& sn1) {
    float sm = a + c, df = a - c;
    float adf = fabsf(df);
    float tb = b + b;
    float ab = fabsf(tb);
    float acmx, acmn;
    if (fabsf(a) > fabsf(c)) { acmx = a; acmn = c; } else { acmx = c; acmn = a; }
    float rt;
    if (adf > ab)       { float t = ab / adf; rt = adf * sqrtf(1.0f + t * t); }
    else if (adf < ab)  { float t = adf / ab; rt = ab * sqrtf(1.0f + t * t); }
    else                { rt = ab * sqrtf(2.0f); }
    int sgn1;
    if (sm < 0.0f) {
        rt1 = 0.5f * (sm - rt); sgn1 = -1;
        rt2 = (acmx / rt1) * acmn - (b / rt1) * b;
    } else if (sm > 0.0f) {
        rt1 = 0.5f * (sm + rt); sgn1 = 1;
        rt2 = (acmx / rt1) * acmn - (b / rt1) * b;
    } else {
        rt1 = 0.5f * rt; rt2 = -0.5f * rt; sgn1 = 1;
    }
    int sgn2;
    float cs;
    if (df >= 0.0f) { cs = df + rt; sgn2 = 1; } else { cs = df - rt; sgn2 = -1; }
    float acs = fabsf(cs);
    if (acs > ab) {
        float ct = -tb / cs;
        sn1 = 1.0f / sqrtf(1.0f + ct * ct);
        cs1 = ct * sn1;
    } else {
        if (ab == 0.0f) { cs1 = 1.0f; sn1 = 0.0f; }
        else {
            float tn = -cs / tb;
            cs1 = 1.0f / sqrtf(1.0f + tn * tn);
            sn1 = tn * cs1;
        }
    }
    if (sgn1 == sgn2) { float tn = cs1; cs1 = -sn1; sn1 = tn; }
}

__device__ void eig3_lapack(float a00, float a01, float a02,
                            float a11, float a12, float a22,
                            float& n0, float& n1, float& n2) {
    const float EPS    = 5.9604645e-8f;     // slamch('E') = 2^-24
    const float EPS2   = EPS * EPS;
    const float SAFMIN = 1.17549435e-38f;   // slamch('S')

    float d[3], e[2];
    float Z[3][3];

    // ---- ssytrd (uplo='L', n=3): one reflector annihilating A(2,0) ----
    if (a02 == 0.0f) {
        d[0] = a00; d[1] = a11; d[2] = a22; e[0] = a01; e[1] = a12;
        Z[0][0] = 1; Z[0][1] = 0; Z[0][2] = 0;
        Z[1][0] = 0; Z[1][1] = 1; Z[1][2] = 0;
        Z[2][0] = 0; Z[2][1] = 0; Z[2][2] = 1;
    } else {
        float alpha = a01;
        float beta  = -signf(lapy2f(alpha, a02), alpha);
        float tau   = (beta - alpha) / beta;
        float v2    = a02 / (alpha - beta);
        // trailing 2x2 update: B -= v w' + w v', w = tau*B*v - (tau/2)(v'(tau*B*v)) v
        float x0 = tau * fmaf(a12, v2, a11);
        float x1 = tau * fmaf(a22, v2, a12);
        float al = -0.5f * tau * fmaf(x1, v2, x0);
        float w0 = x0 + al;
        float w1 = fmaf(al, v2, x1);
        float b00 = a11 - 2.0f * w0;
        float b01 = a12 - (w1 + w0 * v2);
        float b11 = a22 - 2.0f * (v2 * w1);
        d[0] = a00; d[1] = b00; d[2] = b11; e[0] = beta; e[1] = b01;
        // sorgtr (lower): Q(1:2,1:2) = I - tau v v', v = [1, v2]
        Z[0][0] = 1; Z[0][1] = 0;              Z[0][2] = 0;
        Z[1][0] = 0; Z[1][1] = 1.0f - tau;     Z[1][2] = -tau * v2;
        Z[2][0] = 0; Z[2][1] = -tau * v2;      Z[2][2] = 1.0f - tau * v2 * v2;
    }

    // ---- ssteqr (compz='V'-equivalent: Z initialized to Q) ----
    int l1 = 0;
    int jtot = 0;
    while (l1 < 3) {
        if (l1 > 0) e[l1 - 1] = 0.0f;
        int m;
        for (m = l1; m < 2; ++m) {
            float tst = fabsf(e[m]);
            if (tst == 0.0f) break;
            if (tst <= (sqrtf(fabsf(d[m])) * sqrtf(fabsf(d[m + 1]))) * EPS) {
                e[m] = 0.0f;
                break;
            }
        }
        int l = l1, lend = m;
        l1 = m + 1;
        if (lend == l) continue;
        if (fabsf(d[lend]) < fabsf(d[l])) { int t = lend; lend = l; l = t; }

        if (lend > l) {
            // ---------------- QL iteration ----------------
            while (1) {
                int mm;
                for (mm = l; mm < lend; ++mm) {
                    float tst = e[mm] * e[mm];
                    if (tst <= EPS2 * fabsf(d[mm]) * fabsf(d[mm + 1]) + SAFMIN) break;
                }
                m = mm;                      // == lend if none found
                if (m < lend) e[m] = 0.0f;
                float p = d[l];
                if (m == l) { l = l + 1; if (l > lend) break; continue; }
                if (m == l + 1) {
                    float rt1, rt2, c2, s2;
                    slaev2(d[l], e[l], d[l + 1], rt1, rt2, c2, s2);
                    for (int k = 0; k < 3; ++k) {     // slasr 'R','V','B', one pair
                        float t2 = Z[k][l + 1];
                        Z[k][l + 1] = c2 * t2 - s2 * Z[k][l];
                        Z[k][l]     = s2 * t2 + c2 * Z[k][l];
                    }
                    d[l] = rt1; d[l + 1] = rt2; e[l] = 0.0f;
                    l += 2; if (l > lend) break; continue;
                }
                if (jtot >= 90) break;
                jtot++;
                float g = (d[l + 1] - p) / (2.0f * e[l]);
                float r = lapy2f(g, 1.0f);
                g = d[m] - p + e[l] / (g + signf(r, g));
                float s = 1.0f, c = 1.0f;
                p = 0.0f;
                float csv[2], snv[2];
                for (int i = m - 1; i >= l; --i) {
                    float f = s * e[i];
                    float b = c * e[i];
                    slartg(g, f, c, s, r);
                    if (i != m - 1) e[i + 1] = r;
                    g = d[i + 1] - p;
                    float r2 = (d[i] - g) * s + 2.0f * c * b;
                    p = s * r2;
                    d[i + 1] = g + p;
                    g = c * r2 - b;
                    csv[i] = c; snv[i] = -s;
                }
                for (int j = m - 1; j >= l; --j) {    // slasr 'R','V','B'
                    float cj = csv[j], sj = snv[j];
                    for (int k = 0; k < 3; ++k) {
                        float t2 = Z[k][j + 1];
                        Z[k][j + 1] = cj * t2 - sj * Z[k][j];
                        Z[k][j]     = sj * t2 + cj * Z[k][j];
                    }
                }
                d[l] -= p; e[l] = g;
            }
        } else {
            // ---------------- QR iteration ----------------
            while (1) {
                int mm;
                for (mm = l; mm > lend; --mm) {
                    float tst = e[mm - 1] * e[mm - 1];
                    if (tst <= EPS2 * fabsf(d[mm]) * fabsf(d[mm - 1]) + SAFMIN) break;
                }
                m = mm;                      // == lend if none found
                if (m > lend) e[m - 1] = 0.0f;
                float p = d[l];
                if (m == l) { l = l - 1; if (l < lend) break; continue; }
                if (m == l - 1) {
                    float rt1, rt2, c2, s2;
                    slaev2(d[l - 1], e[l - 1], d[l], rt1, rt2, c2, s2);
                    for (int k = 0; k < 3; ++k) {     // slasr 'R','V','F', one pair
                        float t2 = Z[k][l];
                        Z[k][l]     = c2 * t2 - s2 * Z[k][l - 1];
                        Z[k][l - 1] = s2 * t2 + c2 * Z[k][l - 1];
                    }
                    d[l - 1] = rt1; d[l] = rt2; e[l - 1] = 0.0f;
                    l -= 2; if (l < lend) break; continue;
                }
                if (jtot >= 90) break;
                jtot++;
                float g = (d[l - 1] - p) / (2.0f * e[l - 1]);
                float r = lapy2f(g, 1.0f);
                g = d[m] - p + e[l - 1] / (g + signf(r, g));
                float s = 1.0f, c = 1.0f;
                p = 0.0f;
                float csv[2], snv[2];
                for (int i = m; i <= l - 1; ++i) {
                    float f = s * e[i];
                    float b = c * e[i];
                    slartg(g, f, c, s, r);
                    if (i != m) e[i - 1] = r;
                    g = d[i] - p;
                    float r2 = (d[i + 1] - g) * s + 2.0f * c * b;
                    p = s * r2;
                    d[i] = g + p;
                    g = c * r2 - b;
                    csv[i] = c; snv[i] = s;
                }
                for (int j = m; j <= l - 1; ++j) {    // slasr 'R','V','F'
                    float cj = csv[j], sj = snv[j];
                    for (int k = 0; k < 3; ++k) {
                        float t2 = Z[k][j + 1];
                        Z[k][j + 1] = cj * t2 - sj * Z[k][j];
                        Z[k][j]     = sj * t2 + cj * Z[k][j];
                    }
                }
                d[l] -= p; e[l - 1] = g;
            }
        }
    }

    // ---- final selection sort (ascending), swapping eigenvector columns ----
    for (int ii = 1; ii < 3; ++ii) {
        int i = ii - 1, k = i;
        float pv = d[i];
        for (int j = ii; j < 3; ++j)
            if (d[j] < pv) { k = j; pv = d[j]; }
        if (k != i) {
            d[k] = d[i]; d[i] = pv;
            for (int r3 = 0; r3 < 3; ++r3) {
                float t2 = Z[r3][i]; Z[r3][i] = Z[r3][k]; Z[r3][k] = t2;
            }
        }
    }
    n0 = Z[0][0]; n1 = Z[1][0]; n2 = Z[2][0];
}

// ---------------------------------------------------------------------------
// Kernel 1: fused kNN (top-20 smallest sq-distance, self included) + 3x3
// covariance of centered neighbors + smallest-eigenvector normal (LAPACK path).
// Grid: 128 blocks (32 per batch), 256 threads; one query per thread.
// Shared: full batch point set as float4 (x,y,z,|p|^2) = 128 KB.
// ---------------------------------------------------------------------------
__global__ __launch_bounds__(256) void knn_normals_kernel(const float* __restrict__ xyz) {
    extern __shared__ float4 spts[];
    const int b    = blockIdx.x >> 5;
    const int tile = blockIdx.x & 31;
    const int tid  = threadIdx.x;

    const float* xb = xyz + b * NPTS * 3;
    for (int i = tid; i < NPTS; i += 256) {
        float px = xb[i*3+0], py = xb[i*3+1], pz = xb[i*3+2];
        float sq = fmaf(pz, pz, fmaf(py, py, px*px));
        spts[i] = make_float4(px, py, pz, sq);
    }
    __syncthreads();

    const int n = tile * 256 + tid;                      // this thread's query
    const float4 q = spts[n];
    const float qx2 = -2.0f * q.x, qy2 = -2.0f * q.y, qz2 = -2.0f * q.z;

    const float INF = __int_as_float(0x7f800000);
    float hd[KNN]; int hix[KNN];
#pragma unroll
    for (int t = 0; t < KNN; ++t) { hd[t] = INF; hix[t] = 0; }
    float worst = INF; int wpos = 0;

    for (int j = 0; j < NPTS; j += 4) {
        float d[4];
#pragma unroll
        for (int u = 0; u < 4; ++u) {
            float4 p = spts[j + u];
            float m2dot = fmaf(qz2, p.z, fmaf(qy2, p.y, qx2 * p.x));  // -2*dot
            d[u] = (m2dot + q.w) + p.w;   // reference add order: (-2d + sq_n) + sq_m
        }
        float mn = fminf(fminf(d[0], d[1]), fminf(d[2], d[3]));
        if (mn < worst) {
#pragma unroll
            for (int u = 0; u < 4; ++u) {
                if (d[u] < worst) {
#pragma unroll
                    for (int t = 0; t < KNN; ++t)
                        if (t == wpos) { hd[t] = d[u]; hix[t] = j + u; }
                    worst = hd[0]; wpos = 0;
#pragma unroll
                    for (int t = 1; t < KNN; ++t)
                        if (hd[t] > worst) { worst = hd[t]; wpos = t; }
                }
            }
        }
    }

    // Covariance of neighbors centered at the query (self contributes 0)
    float c00 = 0, c01 = 0, c02 = 0, c11 = 0, c12 = 0, c22 = 0;
#pragma unroll
    for (int t = 0; t < KNN; ++t) {
        float4 p = spts[hix[t]];
        float dx = p.x - q.x, dy = p.y - q.y, dz = p.z - q.z;
        c00 = fmaf(dx, dx, c00); c01 = fmaf(dx, dy, c01); c02 = fmaf(dx, dz, c02);
        c11 = fmaf(dy, dy, c11); c12 = fmaf(dy, dz, c12); c22 = fmaf(dz, dz, c22);
    }

    float nx, ny, nz;
    eig3_lapack(c00, c01, c02, c11, c12, c22, nx, ny, nz);

    g_normals[(b*3 + 0) * NPTS + n] = nx;
    g_normals[(b*3 + 1) * NPTS + n] = ny;
    g_normals[(b*3 + 2) * NPTS + n] = nz;
}

// ---------------------------------------------------------------------------
// Kernel 2: h = w1 @ [x; normals] + b1       (GEMM, K=131)
// Tile: 128 channels x 64 points, 256 threads, 8x4 per thread.
// ---------------------------------------------------------------------------
#define WS_STRIDE 133
__global__ __launch_bounds__(256) void gemm1_kernel(const float* __restrict__ x,
                                                    const float* __restrict__ w1,
                                                    const float* __restrict__ b1) {
    extern __shared__ float sm[];
    float* ws = sm;                       // 128 x 133
    float* gs = sm + CCH * WS_STRIDE;     // 131 x 64
    const int b  = blockIdx.y;
    const int n0 = blockIdx.x * TP;
    const int tid = threadIdx.x;

    for (int idx = tid; idx < CCH * KIN1; idx += 256) {
        int c = idx / KIN1, k = idx - c * KIN1;
        ws[c * WS_STRIDE + k] = w1[idx];
    }
    for (int idx = tid; idx < KIN1 * TP; idx += 256) {
        int k = idx >> 6, p = idx & 63;
        float v;
        if (k < CCH) v = x[((b << 7) + k) * NPTS + n0 + p];
        else         v = g_normals[(b * 3 + (k - CCH)) * NPTS + n0 + p];
        gs[k * TP + p] = v;
    }
    __syncthreads();

    const int tr = tid >> 4, tc = tid & 15;
    const int c0 = tr * 8;
    float acc[8][4] = {};
    for (int k = 0; k < KIN1; ++k) {
        float a[8], bb[4];
#pragma unroll
        for (int i = 0; i < 8; ++i) a[i] = ws[(c0 + i) * WS_STRIDE + k];
#pragma unroll
        for (int j = 0; j < 4; ++j) bb[j] = gs[k * TP + tc + 16 * j];
#pragma unroll
        for (int i = 0; i < 8; ++i)
#pragma unroll
            for (int j = 0; j < 4; ++j) acc[i][j] = fmaf(a[i], bb[j], acc[i][j]);
    }
#pragma unroll
    for (int i = 0; i < 8; ++i) {
        float bias = b1[c0 + i];
#pragma unroll
        for (int j = 0; j < 4; ++j)
            g_h[((b << 7) + c0 + i) * NPTS + n0 + tc + 16 * j] = acc[i][j] + bias;
    }
}

// ---------------------------------------------------------------------------
// Kernel 3: per-channel BatchNorm statistics over (B, N); store fused
// scale/shift:  bn(h) = scale*h + shift
// ---------------------------------------------------------------------------
__global__ __launch_bounds__(256) void bn_stats_kernel(const float* __restrict__ gamma,
                                                       const float* __restrict__ beta) {
    const int c = blockIdx.x, tid = threadIdx.x;
    float s = 0.0f, s2 = 0.0f;
    for (int b = 0; b < BATCH; ++b) {
        const float4* p = (const float4*)(g_h + ((b << 7) + c) * NPTS);
        for (int i = tid; i < NPTS / 4; i += 256) {
            float4 v = p[i];
            s  += (v.x + v.y) + (v.z + v.w);
            s2 += fmaf(v.x, v.x, fmaf(v.y, v.y, fmaf(v.z, v.z, v.w * v.w)));
        }
    }
    __shared__ float sh[256], sh2[256];
    sh[tid] = s; sh2[tid] = s2;
    __syncthreads();
    for (int o = 128; o > 0; o >>= 1) {
        if (tid < o) { sh[tid] += sh[tid + o]; sh2[tid] += sh2[tid + o]; }
        __syncthreads();
    }
    if (tid == 0) {
        const float inv = 1.0f / (BATCH * NPTS);
        float mean = sh[0] * inv;
        float var  = sh2[0] * inv - mean * mean;
        float sc   = gamma[c] * rsqrtf(var + 1e-5f);
        g_scale[c] = sc;
        g_shift[c] = beta[c] - mean * sc;
    }
}

// ---------------------------------------------------------------------------
// Kernel 4: out = w2 @ relu(bn(h)) + b2      (GEMM, K=128, BN+ReLU fused into
// the shared-memory load)
// ---------------------------------------------------------------------------
__global__ __launch_bounds__(256) void gemm2_kernel(const float* __restrict__ w2,
                                                    const float* __restrict__ b2,
                                                    float* __restrict__ out) {
    extern __shared__ float sm[];
    float* ws = sm;                       // 128 x 133
    float* gs = sm + CCH * WS_STRIDE;     // 128 x 64
    const int b  = blockIdx.y;
    const int n0 = blockIdx.x * TP;
    const int tid = threadIdx.x;

    for (int idx = tid; idx < CCH * CCH; idx += 256) {
        int c = idx >> 7, k = idx & 127;
        ws[c * WS_STRIDE + k] = w2[idx];
    }
    for (int idx = tid; idx < CCH * TP; idx += 256) {
        int k = idx >> 6, p = idx & 63;
        float hv = g_h[((b << 7) + k) * NPTS + n0 + p];
        gs[k * TP + p] = fmaxf(fmaf(g_scale[k], hv, g_shift[k]), 0.0f);
    }
    __syncthreads();

    const int tr = tid >> 4, tc = tid & 15;
    const int c0 = tr * 8;
    float acc[8][4] = {};
    for (int k = 0; k < CCH; ++k) {
        float a[8], bb[4];
#pragma unroll
        for (int i = 0; i < 8; ++i) a[i] = ws[(c0 + i) * WS_STRIDE + k];
#pragma unroll
        for (int j = 0; j < 4; ++j) bb[j] = gs[k * TP + tc + 16 * j];
#pragma unroll
        for (int i = 0; i < 8; ++i)
#pragma unroll
            for (int j = 0; j < 4; ++j) acc[i][j] = fmaf(a[i], bb[j], acc[i][j]);
    }
#pragma unroll
    for (int i = 0; i < 8; ++i) {
        float bias = b2[c0 + i];
#pragma unroll
        for (int j = 0; j < 4; ++j)
            out[((b << 7) + c0 + i) * NPTS + n0 + tc + 16 * j] = acc[i][j] + bias;
    }
}

// ---------------------------------------------------------------------------
extern "C" void kernel_launch(void* const* d_in, const int* in_sizes, int n_in,
                              void* d_out, int out_size) {
    const float* x     = (const float*)d_in[0];  // [4,128,8192]
    const float* xyz   = (const float*)d_in[1];  // [4,8192,3]
    const float* w1    = (const float*)d_in[2];  // [128,131]
    const float* b1    = (const float*)d_in[3];  // [128]
    const float* gamma = (const float*)d_in[4];  // [128]
    const float* beta  = (const float*)d_in[5];  // [128]
    const float* w2    = (const float*)d_in[6];  // [128,128]
    const float* b2    = (const float*)d_in[7];  // [128]
    float* out = (float*)d_out;                  // [4,128,8192]

    const int SMEM_KNN = NPTS * (int)sizeof(float4);                         // 131072
    const int SMEM_G1  = (CCH * WS_STRIDE + KIN1 * TP) * (int)sizeof(float); // ~101.6KB
    const int SMEM_G2  = (CCH * WS_STRIDE + CCH  * TP) * (int)sizeof(float); // ~100.9KB

    cudaFuncSetAttribute(knn_normals_kernel, cudaFuncAttributeMaxDynamicSharedMemorySize, SMEM_KNN);
    cudaFuncSetAttribute(gemm1_kernel,       cudaFuncAttributeMaxDynamicSharedMemorySize, SMEM_G1);
    cudaFuncSetAttribute(gemm2_kernel,       cudaFuncAttributeMaxDynamicSharedMemorySize, SMEM_G2);

    knn_normals_kernel<<<BATCH * (NPTS / 256), 256, SMEM_KNN>>>(xyz);
    gemm1_kernel<<<dim3(NPTS / TP, BATCH), 256, SMEM_G1>>>(x, w1, b1);
    bn_stats_kernel<<<CCH, 256>>>(gamma, beta);
    gemm2_kernel<<<dim3(NPTS / TP, BATCH), 256, SMEM_G2>>>(w2, b2, out);
}

// round 15
// speedup vs baseline: 2.0077x; 2.0077x over previous
#include <cuda_runtime.h>
#include <cuda_bf16.h>
#include <math.h>

// Problem constants
#define BATCH 4
#define NPTS  8192
#define CCH   128      // channels
#define KIN1  131      // C + 3
#define KNN   20
#define TP    64       // points per GEMM tile

// Scratch (allocation-free rule: __device__ globals)
__device__ float g_normals[BATCH * 3 * NPTS];           // [B,3,N]
__device__ float g_h[BATCH * CCH * NPTS];               // [B,C,N]
__device__ float g_scale[CCH];
__device__ float g_shift[CCH];

// ===========================================================================
// LAPACK-faithful 3x3 symmetric eigensolver: ssytrd + sorgtr + ssteqr
// (verified: rel_err 1.45e-7 in round 12). Unchanged.
// ===========================================================================
__device__ __forceinline__ float signf(float a, float b) {
    return copysignf(fabsf(a), b);
}

__device__ __forceinline__ float lapy2f(float x, float y) {
    float xa = fabsf(x), ya = fabsf(y);
    float w = fmaxf(xa, ya), z = fminf(xa, ya);
    if (z == 0.0f) return w;
    float r = z / w;
    return w * sqrtf(1.0f + r * r);
}

// LAPACK >= 3.10 slartg (c >= 0, r carries sign of f)
__device__ __forceinline__ void slartg(float f, float g, float& c, float& s, float& r) {
    if (g == 0.0f)      { c = 1.0f; s = 0.0f; r = f; }
    else if (f == 0.0f) { c = 0.0f; s = signf(1.0f, g); r = fabsf(g); }
    else {
        float dd = sqrtf(f * f + g * g);
        c = fabsf(f) / dd;
        r = signf(dd, f);
        s = g / r;
    }
}

__device__ __forceinline__ void slaev2(float a, float b, float c,
                                       float& rt1, float& rt2, float& cs1, float& sn1) {
    float sm = a + c, df = a - c;
    float adf = fabsf(df);
    float tb = b + b;
    float ab = fabsf(tb);
    float acmx, acmn;
    if (fabsf(a) > fabsf(c)) { acmx = a; acmn = c; } else { acmx = c; acmn = a; }
    float rt;
    if (adf > ab)       { float t = ab / adf; rt = adf * sqrtf(1.0f + t * t); }
    else if (adf < ab)  { float t = adf / ab; rt = ab * sqrtf(1.0f + t * t); }
    else                { rt = ab * sqrtf(2.0f); }
    int sgn1;
    if (sm < 0.0f) {
        rt1 = 0.5f * (sm - rt); sgn1 = -1;
        rt2 = (acmx / rt1) * acmn - (b / rt1) * b;
    } else if (sm > 0.0f) {
        rt1 = 0.5f * (sm + rt); sgn1 = 1;
        rt2 = (acmx / rt1) * acmn - (b / rt1) * b;
    } else {
        rt1 = 0.5f * rt; rt2 = -0.5f * rt; sgn1 = 1;
    }
    int sgn2;
    float cs;
    if (df >= 0.0f) { cs = df + rt; sgn2 = 1; } else { cs = df - rt; sgn2 = -1; }
    float acs = fabsf(cs);
    if (acs > ab) {
        float ct = -tb / cs;
        sn1 = 1.0f / sqrtf(1.0f + ct * ct);
        cs1 = ct * sn1;
    } else {
        if (ab == 0.0f) { cs1 = 1.0f; sn1 = 0.0f; }
        else {
            float tn = -cs / tb;
            cs1 = 1.0f / sqrtf(1.0f + tn * tn);
            sn1 = tn * cs1;
        }
    }
    if (sgn1 == sgn2) { float tn = cs1; cs1 = -sn1; sn1 = tn; }
}

__device__ void eig3_lapack(float a00, float a01, float a02,
                            float a11, float a12, float a22,
                            float& n0, float& n1, float& n2) {
    const float EPS    = 5.9604645e-8f;     // slamch('E') = 2^-24
    const float EPS2   = EPS * EPS;
    const float SAFMIN = 1.17549435e-38f;   // slamch('S')

    float d[3], e[2];
    float Z[3][3];

    // ---- ssytrd (uplo='L', n=3): one reflector annihilating A(2,0) ----
    if (a02 == 0.0f) {
        d[0] = a00; d[1] = a11; d[2] = a22; e[0] = a01; e[1] = a12;
        Z[0][0] = 1; Z[0][1] = 0; Z[0][2] = 0;
        Z[1][0] = 0; Z[1][1] = 1; Z[1][2] = 0;
        Z[2][0] = 0; Z[2][1] = 0; Z[2][2] = 1;
    } else {
        float alpha = a01;
        float beta  = -signf(lapy2f(alpha, a02), alpha);
        float tau   = (beta - alpha) / beta;
        float v2    = a02 / (alpha - beta);
        float x0 = tau * fmaf(a12, v2, a11);
        float x1 = tau * fmaf(a22, v2, a12);
        float al = -0.5f * tau * fmaf(x1, v2, x0);
        float w0 = x0 + al;
        float w1 = fmaf(al, v2, x1);
        float b00 = a11 - 2.0f * w0;
        float b01 = a12 - (w1 + w0 * v2);
        float b11 = a22 - 2.0f * (v2 * w1);
        d[0] = a00; d[1] = b00; d[2] = b11; e[0] = beta; e[1] = b01;
        Z[0][0] = 1; Z[0][1] = 0;              Z[0][2] = 0;
        Z[1][0] = 0; Z[1][1] = 1.0f - tau;     Z[1][2] = -tau * v2;
        Z[2][0] = 0; Z[2][1] = -tau * v2;      Z[2][2] = 1.0f - tau * v2 * v2;
    }

    // ---- ssteqr ----
    int l1 = 0;
    int jtot = 0;
    while (l1 < 3) {
        if (l1 > 0) e[l1 - 1] = 0.0f;
        int m;
        for (m = l1; m < 2; ++m) {
            float tst = fabsf(e[m]);
            if (tst == 0.0f) break;
            if (tst <= (sqrtf(fabsf(d[m])) * sqrtf(fabsf(d[m + 1]))) * EPS) {
                e[m] = 0.0f;
                break;
            }
        }
        int l = l1, lend = m;
        l1 = m + 1;
        if (lend == l) continue;
        if (fabsf(d[lend]) < fabsf(d[l])) { int t = lend; lend = l; l = t; }

        if (lend > l) {
            // QL
            while (1) {
                int mm;
                for (mm = l; mm < lend; ++mm) {
                    float tst = e[mm] * e[mm];
                    if (tst <= EPS2 * fabsf(d[mm]) * fabsf(d[mm + 1]) + SAFMIN) break;
                }
                m = mm;
                if (m < lend) e[m] = 0.0f;
                float p = d[l];
                if (m == l) { l = l + 1; if (l > lend) break; continue; }
                if (m == l + 1) {
                    float rt1, rt2, c2, s2;
                    slaev2(d[l], e[l], d[l + 1], rt1, rt2, c2, s2);
                    for (int k = 0; k < 3; ++k) {
                        float t2 = Z[k][l + 1];
                        Z[k][l + 1] = c2 * t2 - s2 * Z[k][l];
                        Z[k][l]     = s2 * t2 + c2 * Z[k][l];
                    }
                    d[l] = rt1; d[l + 1] = rt2; e[l] = 0.0f;
                    l += 2; if (l > lend) break; continue;
                }
                if (jtot >= 90) break;
                jtot++;
                float g = (d[l + 1] - p) / (2.0f * e[l]);
                float r = lapy2f(g, 1.0f);
                g = d[m] - p + e[l] / (g + signf(r, g));
                float s = 1.0f, c = 1.0f;
                p = 0.0f;
                float csv[2], snv[2];
                for (int i = m - 1; i >= l; --i) {
                    float f = s * e[i];
                    float b = c * e[i];
                    slartg(g, f, c, s, r);
                    if (i != m - 1) e[i + 1] = r;
                    g = d[i + 1] - p;
                    float r2 = (d[i] - g) * s + 2.0f * c * b;
                    p = s * r2;
                    d[i + 1] = g + p;
                    g = c * r2 - b;
                    csv[i] = c; snv[i] = -s;
                }
                for (int j = m - 1; j >= l; --j) {
                    float cj = csv[j], sj = snv[j];
                    for (int k = 0; k < 3; ++k) {
                        float t2 = Z[k][j + 1];
                        Z[k][j + 1] = cj * t2 - sj * Z[k][j];
                        Z[k][j]     = sj * t2 + cj * Z[k][j];
                    }
                }
                d[l] -= p; e[l] = g;
            }
        } else {
            // QR
            while (1) {
                int mm;
                for (mm = l; mm > lend; --mm) {
                    float tst = e[mm - 1] * e[mm - 1];
                    if (tst <= EPS2 * fabsf(d[mm]) * fabsf(d[mm - 1]) + SAFMIN) break;
                }
                m = mm;
                if (m > lend) e[m - 1] = 0.0f;
                float p = d[l];
                if (m == l) { l = l - 1; if (l < lend) break; continue; }
                if (m == l - 1) {
                    float rt1, rt2, c2, s2;
                    slaev2(d[l - 1], e[l - 1], d[l], rt1, rt2, c2, s2);
                    for (int k = 0; k < 3; ++k) {
                        float t2 = Z[k][l];
                        Z[k][l]     = c2 * t2 - s2 * Z[k][l - 1];
                        Z[k][l - 1] = s2 * t2 + c2 * Z[k][l - 1];
                    }
                    d[l - 1] = rt1; d[l] = rt2; e[l - 1] = 0.0f;
                    l -= 2; if (l < lend) break; continue;
                }
                if (jtot >= 90) break;
                jtot++;
                float g = (d[l - 1] - p) / (2.0f * e[l - 1]);
                float r = lapy2f(g, 1.0f);
                g = d[m] - p + e[l - 1] / (g + signf(r, g));
                float s = 1.0f, c = 1.0f;
                p = 0.0f;
                float csv[2], snv[2];
                for (int i = m; i <= l - 1; ++i) {
                    float f = s * e[i];
                    float b = c * e[i];
                    slartg(g, f, c, s, r);
                    if (i != m) e[i - 1] = r;
                    g = d[i] - p;
                    float r2 = (d[i + 1] - g) * s + 2.0f * c * b;
                    p = s * r2;
                    d[i] = g + p;
                    g = c * r2 - b;
                    csv[i] = c; snv[i] = s;
                }
                for (int j = m; j <= l - 1; ++j) {
                    float cj = csv[j], sj = snv[j];
                    for (int k = 0; k < 3; ++k) {
                        float t2 = Z[k][j + 1];
                        Z[k][j + 1] = cj * t2 - sj * Z[k][j];
                        Z[k][j]     = sj * t2 + cj * Z[k][j];
                    }
                }
                d[l] -= p; e[l - 1] = g;
            }
        }
    }

    // final selection sort (ascending), swapping eigenvector columns
    for (int ii = 1; ii < 3; ++ii) {
        int i = ii - 1, k = i;
        float pv = d[i];
        for (int j = ii; j < 3; ++j)
            if (d[j] < pv) { k = j; pv = d[j]; }
        if (k != i) {
            d[k] = d[i]; d[i] = pv;
            for (int r3 = 0; r3 < 3; ++r3) {
                float t2 = Z[r3][i]; Z[r3][i] = Z[r3][k]; Z[r3][k] = t2;
            }
        }
    }
    n0 = Z[0][0]; n1 = Z[1][0]; n2 = Z[2][0];
}

// ===========================================================================
// Branch-free top-32 maintenance: buffered candidates + bitonic sort/merge.
// td[] sorted ascending (with carried indices ti[]); flush merges a batch of
// up to 32 buffered (d, idx) pairs. All compare-exchanges are predicated
// selects — zero divergent branches.
// ===========================================================================
__device__ __forceinline__ void flush32(const float2* __restrict__ bp, int wr,
                                        float (&td)[32], int (&ti)[32]) {
    const float INF = __int_as_float(0x7f800000);
    float bd[32]; int bi[32];
#pragma unroll
    for (int i = 0; i < 32; ++i) {
        float2 v = bp[i];
        bool ok = i < wr;
        bd[i] = ok ? v.x : INF;
        bi[i] = __float_as_int(v.y);
    }
    // Bitonic sort, DESCENDING
#pragma unroll
    for (int k = 2; k <= 32; k <<= 1) {
#pragma unroll
        for (int j = k >> 1; j > 0; j >>= 1) {
#pragma unroll
            for (int i = 0; i < 32; ++i) {
                int l = i ^ j;
                if (l > i) {
                    bool bigFirst = ((i & k) == 0);
                    bool sw = bigFirst ? (bd[i] < bd[l]) : (bd[i] > bd[l]);
                    float dA = sw ? bd[l] : bd[i];
                    float dB = sw ? bd[i] : bd[l];
                    int   iA = sw ? bi[l] : bi[i];
                    int   iB = sw ? bi[i] : bi[l];
                    bd[i] = dA; bd[l] = dB; bi[i] = iA; bi[l] = iB;
                }
            }
        }
    }
    // Pairwise min: td(asc) ++ bd(desc) is bitonic; keep lower half (bitonic)
#pragma unroll
    for (int i = 0; i < 32; ++i) {
        bool sw = bd[i] < td[i];
        td[i] = sw ? bd[i] : td[i];
        ti[i] = sw ? bi[i] : ti[i];
    }
    // Bitonic merge of bitonic sequence -> ascending
#pragma unroll
    for (int j = 16; j > 0; j >>= 1) {
#pragma unroll
        for (int i = 0; i < 32; ++i) {
            int l = i ^ j;
            if (l > i) {
                bool sw = td[i] > td[l];
                float dA = sw ? td[l] : td[i];
                float dB = sw ? td[i] : td[l];
                int   iA = sw ? ti[l] : ti[i];
                int   iB = sw ? ti[i] : ti[l];
                td[i] = dA; td[l] = dB; ti[i] = iA; ti[l] = iB;
            }
        }
    }
}

// ---------------------------------------------------------------------------
// Kernel 1: fused kNN (top-20 smallest sq-distance) + covariance + normal.
// Grid: 128 blocks (32 per batch), 256 threads; one query per thread.
// Shared: full batch point set (float4, 128KB) + per-thread candidate
// buffers (float2 x 33 per thread, 67.5KB). Scan is branchless; selection
// happens in rare warp-uniform flushes via bitonic networks.
// ---------------------------------------------------------------------------
__global__ __launch_bounds__(256) void knn_normals_kernel(const float* __restrict__ xyz) {
    extern __shared__ float smem_raw[];
    float4* spts = (float4*)smem_raw;                         // [0, 131072)
    float2* bufb = (float2*)(smem_raw + NPTS * 4);            // [131072, 198656)

    const int b    = blockIdx.x >> 5;
    const int tile = blockIdx.x & 31;
    const int tid  = threadIdx.x;

    const float* xb = xyz + b * NPTS * 3;
    for (int i = tid; i < NPTS; i += 256) {
        float px = xb[i*3+0], py = xb[i*3+1], pz = xb[i*3+2];
        float sq = fmaf(pz, pz, fmaf(py, py, px*px));
        spts[i] = make_float4(px, py, pz, sq);
    }
    __syncthreads();

    const int n = tile * 256 + tid;                      // this thread's query
    const float4 q = spts[n];
    const float qx2 = -2.0f * q.x, qy2 = -2.0f * q.y, qz2 = -2.0f * q.z;
    const float qw = q.w;

    const float INF = __int_as_float(0x7f800000);
    float td[32]; int ti[32];
#pragma unroll
    for (int t = 0; t < 32; ++t) { td[t] = INF; ti[t] = 0; }

    float2* bp = bufb + tid * 33;    // per-thread buffer, stride 33 pairs
    int wr = 0;
    float worst = INF;

    for (int j = 0; j < NPTS; j += 8) {
#pragma unroll
        for (int u = 0; u < 8; ++u) {
            float4 p = spts[j + u];
            float m2 = fmaf(qz2, p.z, fmaf(qy2, p.y, qx2 * p.x));  // -2*dot
            float dd = (m2 + qw) + p.w;   // reference add order
            // branchless conditional append: always store, conditionally advance
            bp[wr] = make_float2(dd, __int_as_float(j + u));
            wr += (dd < worst) ? 1 : 0;
        }
        if (__any_sync(0xffffffffu, wr >= 25)) {   // warp-uniform, rare
            flush32(bp, wr, td, ti);
            worst = td[31];
            wr = 0;
        }
    }
    flush32(bp, wr, td, ti);    // final merge (leftovers)

    // Covariance of neighbors centered at the query (self contributes 0)
    float c00 = 0, c01 = 0, c02 = 0, c11 = 0, c12 = 0, c22 = 0;
#pragma unroll
    for (int t = 0; t < KNN; ++t) {
        float4 p = spts[ti[t]];
        float dx = p.x - q.x, dy = p.y - q.y, dz = p.z - q.z;
        c00 = fmaf(dx, dx, c00); c01 = fmaf(dx, dy, c01); c02 = fmaf(dx, dz, c02);
        c11 = fmaf(dy, dy, c11); c12 = fmaf(dy, dz, c12); c22 = fmaf(dz, dz, c22);
    }

    float nx, ny, nz;
    eig3_lapack(c00, c01, c02, c11, c12, c22, nx, ny, nz);

    g_normals[(b*3 + 0) * NPTS + n] = nx;
    g_normals[(b*3 + 1) * NPTS + n] = ny;
    g_normals[(b*3 + 2) * NPTS + n] = nz;
}

// ---------------------------------------------------------------------------
// Kernel 2: h = w1 @ [x; normals] + b1       (GEMM, K=131)
// ---------------------------------------------------------------------------
#define WS_STRIDE 133
__global__ __launch_bounds__(256) void gemm1_kernel(const float* __restrict__ x,
                                                    const float* __restrict__ w1,
                                                    const float* __restrict__ b1) {
    extern __shared__ float sm[];
    float* ws = sm;                       // 128 x 133
    float* gs = sm + CCH * WS_STRIDE;     // 131 x 64
    const int b  = blockIdx.y;
    const int n0 = blockIdx.x * TP;
    const int tid = threadIdx.x;

    for (int idx = tid; idx < CCH * KIN1; idx += 256) {
        int c = idx / KIN1, k = idx - c * KIN1;
        ws[c * WS_STRIDE + k] = w1[idx];
    }
    for (int idx = tid; idx < KIN1 * TP; idx += 256) {
        int k = idx >> 6, p = idx & 63;
        float v;
        if (k < CCH) v = x[((b << 7) + k) * NPTS + n0 + p];
        else         v = g_normals[(b * 3 + (k - CCH)) * NPTS + n0 + p];
        gs[k * TP + p] = v;
    }
    __syncthreads();

    const int tr = tid >> 4, tc = tid & 15;
    const int c0 = tr * 8;
    float acc[8][4] = {};
    for (int k = 0; k < KIN1; ++k) {
        float a[8], bb[4];
#pragma unroll
        for (int i = 0; i < 8; ++i) a[i] = ws[(c0 + i) * WS_STRIDE + k];
#pragma unroll
        for (int j = 0; j < 4; ++j) bb[j] = gs[k * TP + tc + 16 * j];
#pragma unroll
        for (int i = 0; i < 8; ++i)
#pragma unroll
            for (int j = 0; j < 4; ++j) acc[i][j] = fmaf(a[i], bb[j], acc[i][j]);
    }
#pragma unroll
    for (int i = 0; i < 8; ++i) {
        float bias = b1[c0 + i];
#pragma unroll
        for (int j = 0; j < 4; ++j)
            g_h[((b << 7) + c0 + i) * NPTS + n0 + tc + 16 * j] = acc[i][j] + bias;
    }
}

// ---------------------------------------------------------------------------
// Kernel 3: per-channel BatchNorm statistics over (B, N)
// ---------------------------------------------------------------------------
__global__ __launch_bounds__(256) void bn_stats_kernel(const float* __restrict__ gamma,
                                                       const float* __restrict__ beta) {
    const int c = blockIdx.x, tid = threadIdx.x;
    float s = 0.0f, s2 = 0.0f;
    for (int b = 0; b < BATCH; ++b) {
        const float4* p = (const float4*)(g_h + ((b << 7) + c) * NPTS);
        for (int i = tid; i < NPTS / 4; i += 256) {
            float4 v = p[i];
            s  += (v.x + v.y) + (v.z + v.w);
            s2 += fmaf(v.x, v.x, fmaf(v.y, v.y, fmaf(v.z, v.z, v.w * v.w)));
        }
    }
    __shared__ float sh[256], sh2[256];
    sh[tid] = s; sh2[tid] = s2;
    __syncthreads();
    for (int o = 128; o > 0; o >>= 1) {
        if (tid < o) { sh[tid] += sh[tid + o]; sh2[tid] += sh2[tid + o]; }
        __syncthreads();
    }
    if (tid == 0) {
        const float inv = 1.0f / (BATCH * NPTS);
        float mean = sh[0] * inv;
        float var  = sh2[0] * inv - mean * mean;
        float sc   = gamma[c] * rsqrtf(var + 1e-5f);
        g_scale[c] = sc;
        g_shift[c] = beta[c] - mean * sc;
    }
}

// ---------------------------------------------------------------------------
// Kernel 4: out = w2 @ relu(bn(h)) + b2      (GEMM, K=128, BN+ReLU fused)
// ---------------------------------------------------------------------------
__global__ __launch_bounds__(256) void gemm2_kernel(const float* __restrict__ w2,
                                                    const float* __restrict__ b2,
                                                    float* __restrict__ out) {
    extern __shared__ float sm[];
    float* ws = sm;                       // 128 x 133
    float* gs = sm + CCH * WS_STRIDE;     // 128 x 64
    const int b  = blockIdx.y;
    const int n0 = blockIdx.x * TP;
    const int tid = threadIdx.x;

    for (int idx = tid; idx < CCH * CCH; idx += 256) {
        int c = idx >> 7, k = idx & 127;
        ws[c * WS_STRIDE + k] = w2[idx];
    }
    for (int idx = tid; idx < CCH * TP; idx += 256) {
        int k = idx >> 6, p = idx & 63;
        float hv = g_h[((b << 7) + k) * NPTS + n0 + p];
        gs[k * TP + p] = fmaxf(fmaf(g_scale[k], hv, g_shift[k]), 0.0f);
    }
    __syncthreads();

    const int tr = tid >> 4, tc = tid & 15;
    const int c0 = tr * 8;
    float acc[8][4] = {};
    for (int k = 0; k < CCH; ++k) {
        float a[8], bb[4];
#pragma unroll
        for (int i = 0; i < 8; ++i) a[i] = ws[(c0 + i) * WS_STRIDE + k];
#pragma unroll
        for (int j = 0; j < 4; ++j) bb[j] = gs[k * TP + tc + 16 * j];
#pragma unroll
        for (int i = 0; i < 8; ++i)
#pragma unroll
            for (int j = 0; j < 4; ++j) acc[i][j] = fmaf(a[i], bb[j], acc[i][j]);
    }
#pragma unroll
    for (int i = 0; i < 8; ++i) {
        float bias = b2[c0 + i];
#pragma unroll
        for (int j = 0; j < 4; ++j)
            out[((b << 7) + c0 + i) * NPTS + n0 + tc + 16 * j] = acc[i][j] + bias;
    }
}

// ---------------------------------------------------------------------------
extern "C" void kernel_launch(void* const* d_in, const int* in_sizes, int n_in,
                              void* d_out, int out_size) {
    const float* x     = (const float*)d_in[0];  // [4,128,8192]
    const float* xyz   = (const float*)d_in[1];  // [4,8192,3]
    const float* w1    = (const float*)d_in[2];  // [128,131]
    const float* b1    = (const float*)d_in[3];  // [128]
    const float* gamma = (const float*)d_in[4];  // [128]
    const float* beta  = (const float*)d_in[5];  // [128]
    const float* w2    = (const float*)d_in[6];  // [128,128]
    const float* b2    = (const float*)d_in[7];  // [128]
    float* out = (float*)d_out;                  // [4,128,8192]

    const int SMEM_KNN = NPTS * (int)sizeof(float4)
                       + 256 * 33 * (int)sizeof(float2);                     // 131072 + 67584 = 198656
    const int SMEM_G1  = (CCH * WS_STRIDE + KIN1 * TP) * (int)sizeof(float); // ~101.6KB
    const int SMEM_G2  = (CCH * WS_STRIDE + CCH  * TP) * (int)sizeof(float); // ~100.9KB

    cudaFuncSetAttribute(knn_normals_kernel, cudaFuncAttributeMaxDynamicSharedMemorySize, SMEM_KNN);
    cudaFuncSetAttribute(gemm1_kernel,       cudaFuncAttributeMaxDynamicSharedMemorySize, SMEM_G1);
    cudaFuncSetAttribute(gemm2_kernel,       cudaFuncAttributeMaxDynamicSharedMemorySize, SMEM_G2);

    knn_normals_kernel<<<BATCH * (NPTS / 256), 256, SMEM_KNN>>>(xyz);
    gemm1_kernel<<<dim3(NPTS / TP, BATCH), 256, SMEM_G1>>>(x, w1, b1);
    bn_stats_kernel<<<CCH, 256>>>(gamma, beta);
    gemm2_kernel<<<dim3(NPTS / TP, BATCH), 256, SMEM_G2>>>(w2, b2, out);
}

// round 16
// speedup vs baseline: 2.1032x; 1.0476x over previous
#include <cuda_runtime.h>
#include <cuda_bf16.h>
#include <math.h>

// Problem constants
#define BATCH 4
#define NPTS  8192
#define CCH   128      // channels
#define KIN1  131      // C + 3
#define KNN   20
#define TP    64       // points per GEMM tile

// Scratch (allocation-free rule: __device__ globals)
__device__ float g_normals[BATCH * 3 * NPTS];           // [B,3,N]
__device__ float g_h[BATCH * CCH * NPTS];               // [B,C,N]
__device__ float g_scale[CCH];
__device__ float g_shift[CCH];

// ===========================================================================
// LAPACK-faithful 3x3 symmetric eigensolver: ssytrd + sorgtr + ssteqr
// (verified: rel_err 1.45e-7 in round 12). Unchanged.
// ===========================================================================
__device__ __forceinline__ float signf(float a, float b) {
    return copysignf(fabsf(a), b);
}

__device__ __forceinline__ float lapy2f(float x, float y) {
    float xa = fabsf(x), ya = fabsf(y);
    float w = fmaxf(xa, ya), z = fminf(xa, ya);
    if (z == 0.0f) return w;
    float r = z / w;
    return w * sqrtf(1.0f + r * r);
}

// LAPACK >= 3.10 slartg (c >= 0, r carries sign of f)
__device__ __forceinline__ void slartg(float f, float g, float& c, float& s, float& r) {
    if (g == 0.0f)      { c = 1.0f; s = 0.0f; r = f; }
    else if (f == 0.0f) { c = 0.0f; s = signf(1.0f, g); r = fabsf(g); }
    else {
        float dd = sqrtf(f * f + g * g);
        c = fabsf(f) / dd;
        r = signf(dd, f);
        s = g / r;
    }
}

__device__ __forceinline__ void slaev2(float a, float b, float c,
                                       float& rt1, float& rt2, float& cs1, float& sn1) {
    float sm = a + c, df = a - c;
    float adf = fabsf(df);
    float tb = b + b;
    float ab = fabsf(tb);
    float acmx, acmn;
    if (fabsf(a) > fabsf(c)) { acmx = a; acmn = c; } else { acmx = c; acmn = a; }
    float rt;
    if (adf > ab)       { float t = ab / adf; rt = adf * sqrtf(1.0f + t * t); }
    else if (adf < ab)  { float t = adf / ab; rt = ab * sqrtf(1.0f + t * t); }
    else                { rt = ab * sqrtf(2.0f); }
    int sgn1;
    if (sm < 0.0f) {
        rt1 = 0.5f * (sm - rt); sgn1 = -1;
        rt2 = (acmx / rt1) * acmn - (b / rt1) * b;
    } else if (sm > 0.0f) {
        rt1 = 0.5f * (sm + rt); sgn1 = 1;
        rt2 = (acmx / rt1) * acmn - (b / rt1) * b;
    } else {
        rt1 = 0.5f * rt; rt2 = -0.5f * rt; sgn1 = 1;
    }
    int sgn2;
    float cs;
    if (df >= 0.0f) { cs = df + rt; sgn2 = 1; } else { cs = df - rt; sgn2 = -1; }
    float acs = fabsf(cs);
    if (acs > ab) {
        float ct = -tb / cs;
        sn1 = 1.0f / sqrtf(1.0f + ct * ct);
        cs1 = ct * sn1;
    } else {
        if (ab == 0.0f) { cs1 = 1.0f; sn1 = 0.0f; }
        else {
            float tn = -cs / tb;
            cs1 = 1.0f / sqrtf(1.0f + tn * tn);
            sn1 = tn * cs1;
        }
    }
    if (sgn1 == sgn2) { float tn = cs1; cs1 = -sn1; sn1 = tn; }
}

__device__ void eig3_lapack(float a00, float a01, float a02,
                            float a11, float a12, float a22,
                            float& n0, float& n1, float& n2) {
    const float EPS    = 5.9604645e-8f;     // slamch('E') = 2^-24
    const float EPS2   = EPS * EPS;
    const float SAFMIN = 1.17549435e-38f;   // slamch('S')

    float d[3], e[2];
    float Z[3][3];

    // ---- ssytrd (uplo='L', n=3): one reflector annihilating A(2,0) ----
    if (a02 == 0.0f) {
        d[0] = a00; d[1] = a11; d[2] = a22; e[0] = a01; e[1] = a12;
        Z[0][0] = 1; Z[0][1] = 0; Z[0][2] = 0;
        Z[1][0] = 0; Z[1][1] = 1; Z[1][2] = 0;
        Z[2][0] = 0; Z[2][1] = 0; Z[2][2] = 1;
    } else {
        float alpha = a01;
        float beta  = -signf(lapy2f(alpha, a02), alpha);
        float tau   = (beta - alpha) / beta;
        float v2    = a02 / (alpha - beta);
        float x0 = tau * fmaf(a12, v2, a11);
        float x1 = tau * fmaf(a22, v2, a12);
        float al = -0.5f * tau * fmaf(x1, v2, x0);
        float w0 = x0 + al;
        float w1 = fmaf(al, v2, x1);
        float b00 = a11 - 2.0f * w0;
        float b01 = a12 - (w1 + w0 * v2);
        float b11 = a22 - 2.0f * (v2 * w1);
        d[0] = a00; d[1] = b00; d[2] = b11; e[0] = beta; e[1] = b01;
        Z[0][0] = 1; Z[0][1] = 0;              Z[0][2] = 0;
        Z[1][0] = 0; Z[1][1] = 1.0f - tau;     Z[1][2] = -tau * v2;
        Z[2][0] = 0; Z[2][1] = -tau * v2;      Z[2][2] = 1.0f - tau * v2 * v2;
    }

    // ---- ssteqr ----
    int l1 = 0;
    int jtot = 0;
    while (l1 < 3) {
        if (l1 > 0) e[l1 - 1] = 0.0f;
        int m;
        for (m = l1; m < 2; ++m) {
            float tst = fabsf(e[m]);
            if (tst == 0.0f) break;
            if (tst <= (sqrtf(fabsf(d[m])) * sqrtf(fabsf(d[m + 1]))) * EPS) {
                e[m] = 0.0f;
                break;
            }
        }
        int l = l1, lend = m;
        l1 = m + 1;
        if (lend == l) continue;
        if (fabsf(d[lend]) < fabsf(d[l])) { int t = lend; lend = l; l = t; }

        if (lend > l) {
            // QL
            while (1) {
                int mm;
                for (mm = l; mm < lend; ++mm) {
                    float tst = e[mm] * e[mm];
                    if (tst <= EPS2 * fabsf(d[mm]) * fabsf(d[mm + 1]) + SAFMIN) break;
                }
                m = mm;
                if (m < lend) e[m] = 0.0f;
                float p = d[l];
                if (m == l) { l = l + 1; if (l > lend) break; continue; }
                if (m == l + 1) {
                    float rt1, rt2, c2, s2;
                    slaev2(d[l], e[l], d[l + 1], rt1, rt2, c2, s2);
                    for (int k = 0; k < 3; ++k) {
                        float t2 = Z[k][l + 1];
                        Z[k][l + 1] = c2 * t2 - s2 * Z[k][l];
                        Z[k][l]     = s2 * t2 + c2 * Z[k][l];
                    }
                    d[l] = rt1; d[l + 1] = rt2; e[l] = 0.0f;
                    l += 2; if (l > lend) break; continue;
                }
                if (jtot >= 90) break;
                jtot++;
                float g = (d[l + 1] - p) / (2.0f * e[l]);
                float r = lapy2f(g, 1.0f);
                g = d[m] - p + e[l] / (g + signf(r, g));
                float s = 1.0f, c = 1.0f;
                p = 0.0f;
                float csv[2], snv[2];
                for (int i = m - 1; i >= l; --i) {
                    float f = s * e[i];
                    float b = c * e[i];
                    slartg(g, f, c, s, r);
                    if (i != m - 1) e[i + 1] = r;
                    g = d[i + 1] - p;
                    float r2 = (d[i] - g) * s + 2.0f * c * b;
                    p = s * r2;
                    d[i + 1] = g + p;
                    g = c * r2 - b;
                    csv[i] = c; snv[i] = -s;
                }
                for (int j = m - 1; j >= l; --j) {
                    float cj = csv[j], sj = snv[j];
                    for (int k = 0; k < 3; ++k) {
                        float t2 = Z[k][j + 1];
                        Z[k][j + 1] = cj * t2 - sj * Z[k][j];
                        Z[k][j]     = sj * t2 + cj * Z[k][j];
                    }
                }
                d[l] -= p; e[l] = g;
            }
        } else {
            // QR
            while (1) {
                int mm;
                for (mm = l; mm > lend; --mm) {
                    float tst = e[mm - 1] * e[mm - 1];
                    if (tst <= EPS2 * fabsf(d[mm]) * fabsf(d[mm - 1]) + SAFMIN) break;
                }
                m = mm;
                if (m > lend) e[m - 1] = 0.0f;
                float p = d[l];
                if (m == l) { l = l - 1; if (l < lend) break; continue; }
                if (m == l - 1) {
                    float rt1, rt2, c2, s2;
                    slaev2(d[l - 1], e[l - 1], d[l], rt1, rt2, c2, s2);
                    for (int k = 0; k < 3; ++k) {
                        float t2 = Z[k][l];
                        Z[k][l]     = c2 * t2 - s2 * Z[k][l - 1];
                        Z[k][l - 1] = s2 * t2 + c2 * Z[k][l - 1];
                    }
                    d[l - 1] = rt1; d[l] = rt2; e[l - 1] = 0.0f;
                    l -= 2; if (l < lend) break; continue;
                }
                if (jtot >= 90) break;
                jtot++;
                float g = (d[l - 1] - p) / (2.0f * e[l - 1]);
                float r = lapy2f(g, 1.0f);
                g = d[m] - p + e[l - 1] / (g + signf(r, g));
                float s = 1.0f, c = 1.0f;
                p = 0.0f;
                float csv[2], snv[2];
                for (int i = m; i <= l - 1; ++i) {
                    float f = s * e[i];
                    float b = c * e[i];
                    slartg(g, f, c, s, r);
                    if (i != m) e[i - 1] = r;
                    g = d[i] - p;
                    float r2 = (d[i + 1] - g) * s + 2.0f * c * b;
                    p = s * r2;
                    d[i] = g + p;
                    g = c * r2 - b;
                    csv[i] = c; snv[i] = s;
                }
                for (int j = m; j <= l - 1; ++j) {
                    float cj = csv[j], sj = snv[j];
                    for (int k = 0; k < 3; ++k) {
                        float t2 = Z[k][j + 1];
                        Z[k][j + 1] = cj * t2 - sj * Z[k][j];
                        Z[k][j]     = sj * t2 + cj * Z[k][j];
                    }
                }
                d[l] -= p; e[l - 1] = g;
            }
        }
    }

    // final selection sort (ascending), swapping eigenvector columns
    for (int ii = 1; ii < 3; ++ii) {
        int i = ii - 1, k = i;
        float pv = d[i];
        for (int j = ii; j < 3; ++j)
            if (d[j] < pv) { k = j; pv = d[j]; }
        if (k != i) {
            d[k] = d[i]; d[i] = pv;
            for (int r3 = 0; r3 < 3; ++r3) {
                float t2 = Z[r3][i]; Z[r3][i] = Z[r3][k]; Z[r3][k] = t2;
            }
        }
    }
    n0 = Z[0][0]; n1 = Z[1][0]; n2 = Z[2][0];
}

// ===========================================================================
// Branch-free top-32 maintenance: buffered candidates + bitonic sort/merge.
// ===========================================================================
__device__ __forceinline__ void flush32(const float2* __restrict__ bp, int wr,
                                        float (&td)[32], int (&ti)[32]) {
    const float INF = __int_as_float(0x7f800000);
    float bd[32]; int bi[32];
#pragma unroll
    for (int i = 0; i < 32; ++i) {
        float2 v = bp[i];
        bool ok = i < wr;
        bd[i] = ok ? v.x : INF;
        bi[i] = __float_as_int(v.y);
    }
    // Bitonic sort, DESCENDING
#pragma unroll
    for (int k = 2; k <= 32; k <<= 1) {
#pragma unroll
        for (int j = k >> 1; j > 0; j >>= 1) {
#pragma unroll
            for (int i = 0; i < 32; ++i) {
                int l = i ^ j;
                if (l > i) {
                    bool bigFirst = ((i & k) == 0);
                    bool sw = bigFirst ? (bd[i] < bd[l]) : (bd[i] > bd[l]);
                    float dA = sw ? bd[l] : bd[i];
                    float dB = sw ? bd[i] : bd[l];
                    int   iA = sw ? bi[l] : bi[i];
                    int   iB = sw ? bi[i] : bi[l];
                    bd[i] = dA; bd[l] = dB; bi[i] = iA; bi[l] = iB;
                }
            }
        }
    }
    // Pairwise min: td(asc) vs bd(desc) -> bitonic
#pragma unroll
    for (int i = 0; i < 32; ++i) {
        bool sw = bd[i] < td[i];
        td[i] = sw ? bd[i] : td[i];
        ti[i] = sw ? bi[i] : ti[i];
    }
    // Bitonic merge -> ascending
#pragma unroll
    for (int j = 16; j > 0; j >>= 1) {
#pragma unroll
        for (int i = 0; i < 32; ++i) {
            int l = i ^ j;
            if (l > i) {
                bool sw = td[i] > td[l];
                float dA = sw ? td[l] : td[i];
                float dB = sw ? td[i] : td[l];
                int   iA = sw ? ti[l] : ti[i];
                int   iB = sw ? ti[i] : ti[l];
                td[i] = dA; td[l] = dB; ti[i] = iA; ti[l] = iB;
            }
        }
    }
}

// ---------------------------------------------------------------------------
// Kernel 1: fused kNN + covariance + normal. One query per thread.
// Predicated (@p STS.64 via inline PTX — no BSSY, no dead store traffic)
// append into a per-thread smem buffer; warp-uniform bitonic flushes.
// ---------------------------------------------------------------------------
__global__ __launch_bounds__(256) void knn_normals_kernel(const float* __restrict__ xyz) {
    extern __shared__ float smem_raw[];
    float4* spts = (float4*)smem_raw;                         // [0, 131072)
    float2* bufb = (float2*)(smem_raw + NPTS * 4);            // [131072, 198656)

    const int b    = blockIdx.x >> 5;
    const int tile = blockIdx.x & 31;
    const int tid  = threadIdx.x;

    const float* xb = xyz + b * NPTS * 3;
    for (int i = tid; i < NPTS; i += 256) {
        float px = xb[i*3+0], py = xb[i*3+1], pz = xb[i*3+2];
        float sq = fmaf(pz, pz, fmaf(py, py, px*px));
        spts[i] = make_float4(px, py, pz, sq);
    }
    __syncthreads();

    const int n = tile * 256 + tid;                      // this thread's query
    const float4 q = spts[n];
    const float qx2 = -2.0f * q.x, qy2 = -2.0f * q.y, qz2 = -2.0f * q.z;
    const float qw = q.w;

    const float INF = __int_as_float(0x7f800000);
    float td[32]; int ti[32];
#pragma unroll
    for (int t = 0; t < 32; ++t) { td[t] = INF; ti[t] = 0; }

    float2* bp = bufb + tid * 33;    // per-thread buffer, 33 pairs
    const unsigned base = (unsigned)__cvta_generic_to_shared(bp);
    unsigned saddr = base;
    float worst = INF;

    for (int j = 0; j < NPTS; j += 16) {
#pragma unroll
        for (int u = 0; u < 16; ++u) {
            float4 p = spts[j + u];
            float m2 = fmaf(qz2, p.z, fmaf(qy2, p.y, qx2 * p.x));  // -2*dot
            float dd = (m2 + qw) + p.w;                            // reference order
            float idxf = __int_as_float(j + u);
            unsigned inc;
            // Predicated store + advance: single @p STS.64, no branch.
            asm volatile(
                "{\n\t"
                ".reg .pred p;\n\t"
                "setp.lt.f32 p, %2, %3;\n\t"
                "@p st.shared.v2.f32 [%1], {%2, %4};\n\t"
                "selp.u32 %0, 8, 0, p;\n\t"
                "}"
                : "=r"(inc)
                : "r"(saddr), "f"(dd), "f"(worst), "f"(idxf)
                : "memory");
            saddr += inc;
        }
        // group adds <= 16; flush if any lane has >= 17 pending (max idx 31)
        if (__any_sync(0xffffffffu, (saddr - base) >= 17u * 8u)) {
            flush32(bp, (int)((saddr - base) >> 3), td, ti);
            worst = td[31];
            saddr = base;
        }
    }
    flush32(bp, (int)((saddr - base) >> 3), td, ti);    // leftovers

    // Covariance of neighbors centered at the query (self contributes 0)
    float c00 = 0, c01 = 0, c02 = 0, c11 = 0, c12 = 0, c22 = 0;
#pragma unroll
    for (int t = 0; t < KNN; ++t) {
        float4 p = spts[ti[t]];
        float dx = p.x - q.x, dy = p.y - q.y, dz = p.z - q.z;
        c00 = fmaf(dx, dx, c00); c01 = fmaf(dx, dy, c01); c02 = fmaf(dx, dz, c02);
        c11 = fmaf(dy, dy, c11); c12 = fmaf(dy, dz, c12); c22 = fmaf(dz, dz, c22);
    }

    float nx, ny, nz;
    eig3_lapack(c00, c01, c02, c11, c12, c22, nx, ny, nz);

    g_normals[(b*3 + 0) * NPTS + n] = nx;
    g_normals[(b*3 + 1) * NPTS + n] = ny;
    g_normals[(b*3 + 2) * NPTS + n] = nz;
}

// ---------------------------------------------------------------------------
// Kernel 2: h = w1 @ [x; normals] + b1   (GEMM, K=131, vectorized smem loads)
// wsT[k][c] (c contiguous, stride 132) -> 2x LDS.128 for A; points mapped
// tc*4+j -> 1x LDS.128 for B; float4 STG out. FMA order per k unchanged.
// ---------------------------------------------------------------------------
#define WST 132
__global__ __launch_bounds__(256) void gemm1_kernel(const float* __restrict__ x,
                                                    const float* __restrict__ w1,
                                                    const float* __restrict__ b1) {
    extern __shared__ float sm[];
    float* wsT = sm;                      // [131][132]
    float* gs  = sm + KIN1 * WST;         // [131][64]
    const int b  = blockIdx.y;
    const int n0 = blockIdx.x * TP;
    const int tid = threadIdx.x;

    for (int idx = tid; idx < CCH * KIN1; idx += 256) {
        int c = idx / KIN1, k = idx - c * KIN1;
        wsT[k * WST + c] = w1[idx];
    }
    for (int idx = tid; idx < KIN1 * TP; idx += 256) {
        int k = idx >> 6, p = idx & 63;
        float v;
        if (k < CCH) v = x[((b << 7) + k) * NPTS + n0 + p];
        else         v = g_normals[(b * 3 + (k - CCH)) * NPTS + n0 + p];
        gs[k * TP + p] = v;
    }
    __syncthreads();

    const int tr = tid >> 4, tc = tid & 15;
    const int c0 = tr * 8;
    const int p0 = tc * 4;
    float acc[8][4] = {};
#pragma unroll 4
    for (int k = 0; k < KIN1; ++k) {
        float4 a0 = *(const float4*)&wsT[k * WST + c0];
        float4 a1 = *(const float4*)&wsT[k * WST + c0 + 4];
        float4 bv = *(const float4*)&gs[k * TP + p0];
        float a[8] = {a0.x, a0.y, a0.z, a0.w, a1.x, a1.y, a1.z, a1.w};
        float bb[4] = {bv.x, bv.y, bv.z, bv.w};
#pragma unroll
        for (int i = 0; i < 8; ++i)
#pragma unroll
            for (int j = 0; j < 4; ++j) acc[i][j] = fmaf(a[i], bb[j], acc[i][j]);
    }
#pragma unroll
    for (int i = 0; i < 8; ++i) {
        float bias = b1[c0 + i];
        float4 o = make_float4(acc[i][0] + bias, acc[i][1] + bias,
                               acc[i][2] + bias, acc[i][3] + bias);
        *(float4*)&g_h[((b << 7) + c0 + i) * NPTS + n0 + p0] = o;
    }
}

// ---------------------------------------------------------------------------
// Kernel 3: per-channel BatchNorm statistics over (B, N)
// ---------------------------------------------------------------------------
__global__ __launch_bounds__(256) void bn_stats_kernel(const float* __restrict__ gamma,
                                                       const float* __restrict__ beta) {
    const int c = blockIdx.x, tid = threadIdx.x;
    float s = 0.0f, s2 = 0.0f;
    for (int b = 0; b < BATCH; ++b) {
        const float4* p = (const float4*)(g_h + ((b << 7) + c) * NPTS);
        for (int i = tid; i < NPTS / 4; i += 256) {
            float4 v = p[i];
            s  += (v.x + v.y) + (v.z + v.w);
            s2 += fmaf(v.x, v.x, fmaf(v.y, v.y, fmaf(v.z, v.z, v.w * v.w)));
        }
    }
    __shared__ float sh[256], sh2[256];
    sh[tid] = s; sh2[tid] = s2;
    __syncthreads();
    for (int o = 128; o > 0; o >>= 1) {
        if (tid < o) { sh[tid] += sh[tid + o]; sh2[tid] += sh2[tid + o]; }
        __syncthreads();
    }
    if (tid == 0) {
        const float inv = 1.0f / (BATCH * NPTS);
        float mean = sh[0] * inv;
        float var  = sh2[0] * inv - mean * mean;
        float sc   = gamma[c] * rsqrtf(var + 1e-5f);
        g_scale[c] = sc;
        g_shift[c] = beta[c] - mean * sc;
    }
}

// ---------------------------------------------------------------------------
// Kernel 4: out = w2 @ relu(bn(h)) + b2   (GEMM, K=128, BN+ReLU fused,
// vectorized like gemm1)
// ---------------------------------------------------------------------------
__global__ __launch_bounds__(256) void gemm2_kernel(const float* __restrict__ w2,
                                                    const float* __restrict__ b2,
                                                    float* __restrict__ out) {
    extern __shared__ float sm[];
    float* wsT = sm;                      // [128][132]
    float* gs  = sm + CCH * WST;          // [128][64]
    const int b  = blockIdx.y;
    const int n0 = blockIdx.x * TP;
    const int tid = threadIdx.x;

    for (int idx = tid; idx < CCH * CCH; idx += 256) {
        int c = idx >> 7, k = idx & 127;
        wsT[k * WST + c] = w2[idx];
    }
    for (int idx = tid; idx < CCH * TP; idx += 256) {
        int k = idx >> 6, p = idx & 63;
        float hv = g_h[((b << 7) + k) * NPTS + n0 + p];
        gs[k * TP + p] = fmaxf(fmaf(g_scale[k], hv, g_shift[k]), 0.0f);
    }
    __syncthreads();

    const int tr = tid >> 4, tc = tid & 15;
    const int c0 = tr * 8;
    const int p0 = tc * 4;
    float acc[8][4] = {};
#pragma unroll 4
    for (int k = 0; k < CCH; ++k) {
        float4 a0 = *(const float4*)&wsT[k * WST + c0];
        float4 a1 = *(const float4*)&wsT[k * WST + c0 + 4];
        float4 bv = *(const float4*)&gs[k * TP + p0];
        float a[8] = {a0.x, a0.y, a0.z, a0.w, a1.x, a1.y, a1.z, a1.w};
        float bb[4] = {bv.x, bv.y, bv.z, bv.w};
#pragma unroll
        for (int i = 0; i < 8; ++i)
#pragma unroll
            for (int j = 0; j < 4; ++j) acc[i][j] = fmaf(a[i], bb[j], acc[i][j]);
    }
#pragma unroll
    for (int i = 0; i < 8; ++i) {
        float bias = b2[c0 + i];
        float4 o = make_float4(acc[i][0] + bias, acc[i][1] + bias,
                               acc[i][2] + bias, acc[i][3] + bias);
        *(float4*)&out[((b << 7) + c0 + i) * NPTS + n0 + p0] = o;
    }
}

// ---------------------------------------------------------------------------
extern "C" void kernel_launch(void* const* d_in, const int* in_sizes, int n_in,
                              void* d_out, int out_size) {
    const float* x     = (const float*)d_in[0];  // [4,128,8192]
    const float* xyz   = (const float*)d_in[1];  // [4,8192,3]
    const float* w1    = (const float*)d_in[2];  // [128,131]
    const float* b1    = (const float*)d_in[3];  // [128]
    const float* gamma = (const float*)d_in[4];  // [128]
    const float* beta  = (const float*)d_in[5];  // [128]
    const float* w2    = (const float*)d_in[6];  // [128,128]
    const float* b2    = (const float*)d_in[7];  // [128]
    float* out = (float*)d_out;                  // [4,128,8192]

    const int SMEM_KNN = NPTS * (int)sizeof(float4)
                       + 256 * 33 * (int)sizeof(float2);                   // 198656
    const int SMEM_G1  = (KIN1 * WST + KIN1 * TP) * (int)sizeof(float);    // 102704
    const int SMEM_G2  = (CCH * WST + CCH * TP) * (int)sizeof(float);      // 100352

    cudaFuncSetAttribute(knn_normals_kernel, cudaFuncAttributeMaxDynamicSharedMemorySize, SMEM_KNN);
    cudaFuncSetAttribute(gemm1_kernel,       cudaFuncAttributeMaxDynamicSharedMemorySize, SMEM_G1);
    cudaFuncSetAttribute(gemm2_kernel,       cudaFuncAttributeMaxDynamicSharedMemorySize, SMEM_G2);

    knn_normals_kernel<<<BATCH * (NPTS / 256), 256, SMEM_KNN>>>(xyz);
    gemm1_kernel<<<dim3(NPTS / TP, BATCH), 256, SMEM_G1>>>(x, w1, b1);
    bn_stats_kernel<<<CCH, 256>>>(gamma, beta);
    gemm2_kernel<<<dim3(NPTS / TP, BATCH), 256, SMEM_G2>>>(w2, b2, out);
}